// round 1
// baseline (speedup 1.0000x reference)
#include <cuda_runtime.h>

#define NNODES 50000
#define NEDGES 800000
#define HDIM   96

// ---------------- scratch (static device globals: allowed) ----------------
__device__ __align__(128) float g_bufA[NNODES * HDIM];
__device__ __align__(128) float g_bufB[NNODES * HDIM];
__device__ __align__(128) float g_bufC[NNODES * HDIM];
__device__ __align__(128) float g_bufD[NNODES * HDIM];
__device__ int   g_deg[NNODES];
__device__ float g_dis[NNODES];      // rsqrt(deg+1)
__device__ float g_invdeg[NNODES];   // 1/(deg+1)
__device__ int   g_row_ptr[NNODES + 1];
__device__ int   g_cursor[NNODES];
__device__ int   g_csr_src[NEDGES];

// ---------------- graph build ----------------
__global__ void k_zero_deg() {
    int i = blockIdx.x * blockDim.x + threadIdx.x;
    if (i < NNODES) g_deg[i] = 0;
}

__global__ void k_hist(const int* __restrict__ dst) {
    int i = blockIdx.x * blockDim.x + threadIdx.x;
    if (i < NEDGES) atomicAdd(&g_deg[dst[i]], 1);
}

__global__ void k_degnorm() {
    int i = blockIdx.x * blockDim.x + threadIdx.x;
    if (i < NNODES) {
        float d = (float)(g_deg[i] + 1);
        g_dis[i] = rsqrtf(d);
        g_invdeg[i] = 1.0f / d;
    }
}

// single-block exclusive scan of g_deg -> g_row_ptr (n = 50000, 49 chunks)
__global__ void k_scan() {
    __shared__ int s_carry;
    __shared__ int wsum[32];
    const int n = NNODES;
    int tid = threadIdx.x;
    if (tid == 0) s_carry = 0;
    __syncthreads();
    for (int base = 0; base < n; base += blockDim.x) {
        int i = base + tid;
        int v = (i < n) ? g_deg[i] : 0;
        int lane = tid & 31, wid = tid >> 5;
        int x = v;
        #pragma unroll
        for (int o = 1; o < 32; o <<= 1) {
            int y = __shfl_up_sync(0xffffffffu, x, o);
            if (lane >= o) x += y;
        }
        if (lane == 31) wsum[wid] = x;
        __syncthreads();
        if (wid == 0) {
            int nw = blockDim.x >> 5;
            int s = (lane < nw) ? wsum[lane] : 0;
            #pragma unroll
            for (int o = 1; o < 32; o <<= 1) {
                int y = __shfl_up_sync(0xffffffffu, s, o);
                if (lane >= o) s += y;
            }
            wsum[lane] = s;
        }
        __syncthreads();
        int incl = x + (wid > 0 ? wsum[wid - 1] : 0);
        int carry = s_carry;
        if (i < n) g_row_ptr[i] = carry + incl - v;   // exclusive
        __syncthreads();
        if (tid == blockDim.x - 1) s_carry = carry + incl;
        __syncthreads();
    }
    if (tid == 0) g_row_ptr[n] = s_carry;
}

__global__ void k_cursor_init() {
    int i = blockIdx.x * blockDim.x + threadIdx.x;
    if (i < NNODES) g_cursor[i] = g_row_ptr[i];
}

__global__ void k_scatter(const int* __restrict__ src, const int* __restrict__ dst) {
    int i = blockIdx.x * blockDim.x + threadIdx.x;
    if (i < NEDGES) {
        int d = dst[i];
        int p = atomicAdd(&g_cursor[d], 1);
        g_csr_src[p] = src[i];
    }
}

// ---------------- GEMM: out[N,HOUT] = in[N,96] @ W[HOUT,96]^T (+ bias/emb/relu/residual)
enum { F_BIAS = 1, F_EMB = 2, F_RELU = 4, F_RES = 8 };

template <int HOUT, unsigned FLAGS>
__global__ void __launch_bounds__(128) k_gemm(
    const float* __restrict__ in, const float* __restrict__ W,
    const float* __restrict__ bias,
    const float* __restrict__ emb, const int* __restrict__ t,
    const float* __restrict__ res,
    float* __restrict__ out, int nrows)
{
    const int HIN = HDIM;       // 96
    const int RPB = 128;        // rows per block, == blockDim.x
    const int XSTR = 100;       // padded row stride (conflict-avoidance + f4 align)
    extern __shared__ float sm[];
    float* Xsh = sm;                       // RPB * XSTR
    float* Wsh = sm + RPB * XSTR;          // [k*HOUT + j] = W[j*HIN + k]
    int tid = threadIdx.x;
    int r0 = blockIdx.x * RPB;

    // stage W transposed into smem
    for (int idx = tid; idx < HIN * HOUT; idx += RPB) {
        int k = idx / HOUT, j = idx - k * HOUT;
        Wsh[idx] = W[j * HIN + k];
    }
    // stage X tile coalesced (float4)
    int nrow_blk = nrows - r0; if (nrow_blk > RPB) nrow_blk = RPB;
    const float4* in4 = reinterpret_cast<const float4*>(in + (size_t)r0 * HIN);
    int total4 = nrow_blk * (HIN / 4);
    for (int i = tid; i < RPB * (HIN / 4); i += RPB) {
        if (i < total4) {
            float4 v = in4[i];
            int row = i / (HIN / 4);
            int col = (i - row * (HIN / 4)) * 4;
            *reinterpret_cast<float4*>(&Xsh[row * XSTR + col]) = v;
        }
    }
    __syncthreads();

    unsigned long long acc[HOUT / 2];
    #pragma unroll
    for (int j = 0; j < HOUT / 2; j++) acc[j] = 0ull;

    const float* xr = &Xsh[tid * XSTR];
    #pragma unroll 4
    for (int k = 0; k < HIN; k++) {
        float xv = xr[k];
        unsigned long long xv2;
        asm("mov.b64 %0, {%1, %1};" : "=l"(xv2) : "f"(xv));
        const unsigned long long* w2 =
            reinterpret_cast<const unsigned long long*>(&Wsh[k * HOUT]);
        #pragma unroll
        for (int j = 0; j < HOUT / 2; j++) {
            asm("fma.rn.f32x2 %0, %1, %2, %0;"
                : "+l"(acc[j]) : "l"(xv2), "l"(w2[j]));
        }
    }

    int row = r0 + tid;
    if (row < nrows) {
        int t0 = 0;
        if (FLAGS & F_EMB) t0 = t[0];
        float* orow = out + (size_t)row * HOUT;
        const float* rrow = (FLAGS & F_RES) ? (res + (size_t)row * HOUT) : nullptr;
        #pragma unroll
        for (int j = 0; j < HOUT / 2; j++) {
            float2 v = *reinterpret_cast<float2*>(&acc[j]);
            float v0 = v.x, v1 = v.y;
            if (FLAGS & F_BIAS) { v0 += bias[2 * j];            v1 += bias[2 * j + 1]; }
            if (FLAGS & F_EMB)  { v0 += emb[t0 * HDIM + 2 * j]; v1 += emb[t0 * HDIM + 2 * j + 1]; }
            if (FLAGS & F_RELU) { v0 = fmaxf(v0, 0.0f);         v1 = fmaxf(v1, 0.0f); }
            if (FLAGS & F_RES)  { v0 += rrow[2 * j];            v1 += rrow[2 * j + 1]; }
            *reinterpret_cast<float2*>(&orow[2 * j]) = make_float2(v0, v1);
        }
    }
}

// ---------------- GCN aggregation: one warp per dst node ----------------
// out[v] = dis[v] * sum_{e in CSR[v]} dis[src_e] * xw[src_e]  +  xw[v]/deg[v] + bias
__global__ void k_agg(const float* __restrict__ xw, const float* __restrict__ bias,
                      float* __restrict__ out)
{
    int warp = (blockIdx.x * blockDim.x + threadIdx.x) >> 5;
    int lane = threadIdx.x & 31;
    if (warp >= NNODES) return;
    int v = warp;
    int s = g_row_ptr[v], e = g_row_ptr[v + 1];
    float a0 = 0.f, a1 = 0.f, a2 = 0.f;
    for (int i = s; i < e; i++) {
        int u = g_csr_src[i];
        float wn = g_dis[u];
        const float* r = xw + (size_t)u * HDIM;
        a0 += wn * r[lane];
        a1 += wn * r[lane + 32];
        a2 += wn * r[lane + 64];
    }
    float dv = g_dis[v];
    float iv = g_invdeg[v];
    const float* sr = xw + (size_t)v * HDIM;
    float* o = out + (size_t)v * HDIM;
    o[lane]      = a0 * dv + sr[lane]      * iv + bias[lane];
    o[lane + 32] = a1 * dv + sr[lane + 32] * iv + bias[lane + 32];
    o[lane + 64] = a2 * dv + sr[lane + 64] * iv + bias[lane + 64];
}

// ---------------- launch ----------------
extern "C" void kernel_launch(void* const* d_in, const int* in_sizes, int n_in,
                              void* d_out, int out_size)
{
    const float* x       = (const float*)d_in[0];
    const int*   t       = (const int*)  d_in[1];
    const int*   ei      = (const int*)  d_in[2];
    const float* emb     = (const float*)d_in[3];
    const float* fw_W    = (const float*)d_in[4];
    const float* fw_b    = (const float*)d_in[5];
    const float* pre_W   = (const float*)d_in[6];
    const float* pre_b   = (const float*)d_in[7];
    const float* conv_W  = (const float*)d_in[8];
    const float* conv_b  = (const float*)d_in[9];
    const float* post_W1 = (const float*)d_in[10];
    const float* post_b1 = (const float*)d_in[11];
    const float* post_W2 = (const float*)d_in[12];
    const float* post_b2 = (const float*)d_in[13];
    const float* fin_W   = (const float*)d_in[14];
    const float* fin_b   = (const float*)d_in[15];
    float* out = (float*)d_out;

    const int* src = ei;
    const int* dst = ei + NEDGES;

    float *A, *B, *C, *D;
    cudaGetSymbolAddress((void**)&A, g_bufA);
    cudaGetSymbolAddress((void**)&B, g_bufB);
    cudaGetSymbolAddress((void**)&C, g_bufC);
    cudaGetSymbolAddress((void**)&D, g_bufD);

    const int SMEM96 = (128 * 100 + 96 * 96) * 4;  // ~88 KB
    const int SMEM32 = (128 * 100 + 96 * 32) * 4;  // ~63 KB
    cudaFuncSetAttribute(k_gemm<96, F_BIAS>,          cudaFuncAttributeMaxDynamicSharedMemorySize, SMEM96);
    cudaFuncSetAttribute(k_gemm<96, F_BIAS | F_EMB>,  cudaFuncAttributeMaxDynamicSharedMemorySize, SMEM96);
    cudaFuncSetAttribute(k_gemm<96, 0u>,              cudaFuncAttributeMaxDynamicSharedMemorySize, SMEM96);
    cudaFuncSetAttribute(k_gemm<96, F_BIAS | F_RELU>, cudaFuncAttributeMaxDynamicSharedMemorySize, SMEM96);
    cudaFuncSetAttribute(k_gemm<96, F_BIAS | F_RES>,  cudaFuncAttributeMaxDynamicSharedMemorySize, SMEM96);
    cudaFuncSetAttribute(k_gemm<32, F_BIAS>,          cudaFuncAttributeMaxDynamicSharedMemorySize, SMEM32);

    // --- graph build (once per launch, reused by both layers) ---
    k_zero_deg   <<<(NNODES + 255) / 256, 256>>>();
    k_hist       <<<(NEDGES + 255) / 256, 256>>>(dst);
    k_degnorm    <<<(NNODES + 255) / 256, 256>>>();
    k_scan       <<<1, 1024>>>();
    k_cursor_init<<<(NNODES + 255) / 256, 256>>>();
    k_scatter    <<<(NEDGES + 255) / 256, 256>>>(src, dst);

    const int GG = (NNODES + 127) / 128;
    const int AGG_BLOCKS = (NNODES * 32 + 255) / 256;

    // first layer: A = x @ fw_W^T + fw_b
    k_gemm<96, F_BIAS><<<GG, 128, SMEM96>>>(x, fw_W, fw_b, nullptr, nullptr, nullptr, A, NNODES);

    for (int l = 0; l < 2; l++) {
        const float* pW  = pre_W   + l * HDIM * HDIM;
        const float* pb  = pre_b   + l * HDIM;
        const float* cW  = conv_W  + l * HDIM * HDIM;
        const float* cb  = conv_b  + l * HDIM;
        const float* w1  = post_W1 + l * HDIM * HDIM;
        const float* b1  = post_b1 + l * HDIM;
        const float* w2  = post_W2 + l * HDIM * HDIM;
        const float* b2  = post_b2 + l * HDIM;

        // B = A @ pre_W^T + pre_b + emb[t]
        k_gemm<96, F_BIAS | F_EMB><<<GG, 128, SMEM96>>>(A, pW, pb, emb, t, nullptr, B, NNODES);
        // C = B @ conv_W^T   (xw; conv bias applied post-aggregation)
        k_gemm<96, 0u><<<GG, 128, SMEM96>>>(B, cW, nullptr, nullptr, nullptr, nullptr, C, NNODES);
        // D = GCN aggregate(C) + conv_b
        k_agg<<<AGG_BLOCKS, 256>>>(C, cb, D);
        // B = relu(D @ post_W1^T + post_b1)
        k_gemm<96, F_BIAS | F_RELU><<<GG, 128, SMEM96>>>(D, w1, b1, nullptr, nullptr, nullptr, B, NNODES);
        // C = B @ post_W2^T + post_b2 + A   (residual)
        k_gemm<96, F_BIAS | F_RES><<<GG, 128, SMEM96>>>(B, w2, b2, nullptr, nullptr, A, C, NNODES);
        // swap: next-layer h lives in C
        float* tmp = A; A = C; C = tmp;
    }

    // out = A @ fin_W^T + fin_b
    k_gemm<32, F_BIAS><<<GG, 128, SMEM32>>>(A, fin_W, fin_b, nullptr, nullptr, nullptr, out, NNODES);
}

// round 2
// speedup vs baseline: 1.7247x; 1.7247x over previous
#include <cuda_runtime.h>

#define NNODES 50000
#define NEDGES 800000
#define HDIM   96

typedef unsigned long long u64;

// ---------------- scratch ----------------
__device__ __align__(128) float g_bufA[NNODES * HDIM];
__device__ __align__(128) float g_bufB[NNODES * HDIM];
__device__ __align__(128) float g_bufC[NNODES * HDIM];
__device__ __align__(128) float g_bufD[NNODES * HDIM];
__device__ __align__(128) float g_Wc[HDIM * HDIM];
__device__ __align__(128) float g_bc[HDIM];
__device__ int   g_deg[NNODES];
__device__ float g_dis[NNODES];
__device__ float g_invdeg[NNODES];
__device__ int   g_row_ptr[NNODES + 1];
__device__ int   g_cursor[NNODES];
__device__ int   g_csr_src[NEDGES];
__device__ int   g_part[128];

// ---------------- graph build ----------------
__global__ void k_zero_deg() {
    int i = blockIdx.x * blockDim.x + threadIdx.x;
    if (i < NNODES) g_deg[i] = 0;
}

__global__ void k_hist(const int* __restrict__ dst) {
    int i = blockIdx.x * blockDim.x + threadIdx.x;
    if (i < NEDGES) atomicAdd(&g_deg[dst[i]], 1);
}

#define SCAN_B 512
#define SCAN_NBLK ((NNODES + SCAN_B - 1) / SCAN_B)   // 98

__global__ void k_scan_part() {
    __shared__ int ws[16];
    int i = blockIdx.x * SCAN_B + threadIdx.x;
    int v = (i < NNODES) ? g_deg[i] : 0;
    int lane = threadIdx.x & 31, wid = threadIdx.x >> 5;
    int s = v;
    #pragma unroll
    for (int o = 16; o > 0; o >>= 1) s += __shfl_down_sync(0xffffffffu, s, o);
    if (lane == 0) ws[wid] = s;
    __syncthreads();
    if (wid == 0) {
        int t = (lane < (SCAN_B / 32)) ? ws[lane] : 0;
        #pragma unroll
        for (int o = 16; o > 0; o >>= 1) t += __shfl_down_sync(0xffffffffu, t, o);
        if (lane == 0) g_part[blockIdx.x] = t;
    }
}

__global__ void k_scan_mid() {
    // serial exclusive scan of SCAN_NBLK partials (tiny)
    int acc = 0;
    for (int j = 0; j < SCAN_NBLK; j++) {
        int t = g_part[j];
        g_part[j] = acc;
        acc += t;
    }
    g_row_ptr[NNODES] = acc;
}

__global__ void k_scan_apply() {
    __shared__ int ws[17];
    int i = blockIdx.x * SCAN_B + threadIdx.x;
    int v = (i < NNODES) ? g_deg[i] : 0;
    int lane = threadIdx.x & 31, wid = threadIdx.x >> 5;
    int x = v;
    #pragma unroll
    for (int o = 1; o < 32; o <<= 1) {
        int y = __shfl_up_sync(0xffffffffu, x, o);
        if (lane >= o) x += y;
    }
    if (lane == 31) ws[wid] = x;
    __syncthreads();
    if (wid == 0) {
        int nw = SCAN_B / 32;
        int s = (lane < nw) ? ws[lane] : 0;
        #pragma unroll
        for (int o = 1; o < 32; o <<= 1) {
            int y = __shfl_up_sync(0xffffffffu, s, o);
            if (lane >= o) s += y;
        }
        if (lane < nw) ws[lane] = s;
    }
    __syncthreads();
    int excl = x - v + (wid > 0 ? ws[wid - 1] : 0) + g_part[blockIdx.x];
    if (i < NNODES) {
        g_row_ptr[i] = excl;
        g_cursor[i] = excl;
        float d = (float)(v + 1);
        g_dis[i] = rsqrtf(d);
        g_invdeg[i] = 1.0f / d;
    }
}

__global__ void k_scatter(const int* __restrict__ src, const int* __restrict__ dst) {
    int i = blockIdx.x * blockDim.x + threadIdx.x;
    if (i < NEDGES) {
        int d = dst[i];
        int p = atomicAdd(&g_cursor[d], 1);
        g_csr_src[p] = src[i];
    }
}

// ---------------- weight composition: Wc = convW @ preW ; bc = convW @ (pre_b + emb[t]) ----
__global__ void k_compose(const float* __restrict__ preW, const float* __restrict__ pre_b,
                          const float* __restrict__ convW,
                          const float* __restrict__ emb, const int* __restrict__ t)
{
    __shared__ float cw[HDIM];
    __shared__ float red[HDIM];
    int j = blockIdx.x, k = threadIdx.x;
    cw[k] = convW[j * HDIM + k];
    __syncthreads();
    float acc = 0.f;
    #pragma unroll 4
    for (int m = 0; m < HDIM; m++) acc += cw[m] * preW[m * HDIM + k];
    g_Wc[j * HDIM + k] = acc;
    int t0 = t[0];
    red[k] = cw[k] * (pre_b[k] + emb[t0 * HDIM + k]);
    __syncthreads();
    if (k == 0) {
        float s = 0.f;
        for (int m = 0; m < HDIM; m++) s += red[m];
        g_bc[j] = s;
    }
}

// ---------------- register-blocked GEMM ----------------
// out[N,HOUT] = in[N,96] @ W[HOUT,96]^T  (+ bias/relu/residual)
// block: 256 thr, 128 rows. thread: 4 rows (ri, ri+32, ri+64, ri+96) x CPT cols (c*CPT..)
enum { F_BIAS = 1, F_RELU = 4, F_RES = 8 };

template <int HOUT, unsigned FLAGS>
__global__ void __launch_bounds__(256, 2) k_gemm(
    const float* __restrict__ in, const float* __restrict__ W,
    const float* __restrict__ bias, const float* __restrict__ res,
    float* __restrict__ out, int nrows)
{
    const int HIN = HDIM;
    const int RPB = 128;
    const int XSTR = 100;                 // 400 B row stride (16B-aligned, conflict-free)
    const int CPT = HOUT / 8;             // cols per thread (12 or 4)
    extern __shared__ float sm[];
    float* Xsh = sm;                      // RPB * XSTR
    float* Wsh = sm + RPB * XSTR;         // [k*HOUT + j] = W[j*HIN + k]
    int tid = threadIdx.x;
    int r0 = blockIdx.x * RPB;
    int c = tid & 7;
    int ri = tid >> 3;                    // 0..31

    // stage W transposed
    for (int idx = tid; idx < HIN * HOUT; idx += 256) {
        int k = idx / HOUT, j = idx - k * HOUT;
        Wsh[idx] = W[j * HIN + k];
    }
    // stage X tile (float4, coalesced)
    int nrow_blk = nrows - r0; if (nrow_blk > RPB) nrow_blk = RPB;
    const float4* in4 = reinterpret_cast<const float4*>(in + (size_t)r0 * HIN);
    int total4 = nrow_blk * (HIN / 4);
    for (int i = tid; i < RPB * (HIN / 4); i += 256) {
        if (i < total4) {
            float4 v = in4[i];
            int row = i / (HIN / 4);
            int col = (i - row * (HIN / 4)) * 4;
            *reinterpret_cast<float4*>(&Xsh[row * XSTR + col]) = v;
        }
    }
    __syncthreads();

    u64 acc[4][CPT / 2];
    #pragma unroll
    for (int r = 0; r < 4; r++)
        #pragma unroll
        for (int j = 0; j < CPT / 2; j++) acc[r][j] = 0ull;

    #pragma unroll 2
    for (int k0 = 0; k0 < HIN; k0 += 4) {
        float xr[4][4];
        #pragma unroll
        for (int r = 0; r < 4; r++)
            *reinterpret_cast<float4*>(xr[r]) =
                *reinterpret_cast<const float4*>(&Xsh[(ri + 32 * r) * XSTR + k0]);

        #pragma unroll
        for (int kk = 0; kk < 4; kk++) {
            float wv[CPT];
            #pragma unroll
            for (int q = 0; q < CPT / 4; q++)
                *reinterpret_cast<float4*>(&wv[4 * q]) =
                    *reinterpret_cast<const float4*>(&Wsh[(k0 + kk) * HOUT + c * CPT + 4 * q]);
            const u64* w2 = reinterpret_cast<const u64*>(wv);
            #pragma unroll
            for (int r = 0; r < 4; r++) {
                u64 xv2;
                asm("mov.b64 %0, {%1, %1};" : "=l"(xv2) : "f"(xr[r][kk]));
                #pragma unroll
                for (int j = 0; j < CPT / 2; j++)
                    asm("fma.rn.f32x2 %0, %1, %2, %0;"
                        : "+l"(acc[r][j]) : "l"(xv2), "l"(w2[j]));
            }
        }
    }

    #pragma unroll
    for (int r = 0; r < 4; r++) {
        int row = r0 + ri + 32 * r;
        if (row < nrows) {
            float* orow = out + (size_t)row * HOUT + c * CPT;
            const float* brow = bias + c * CPT;
            const float* rrow = (FLAGS & F_RES) ? (res + (size_t)row * HOUT + c * CPT) : nullptr;
            #pragma unroll
            for (int j = 0; j < CPT / 2; j++) {
                float2 v = *reinterpret_cast<float2*>(&acc[r][j]);
                float v0 = v.x, v1 = v.y;
                if (FLAGS & F_BIAS) { v0 += brow[2 * j];  v1 += brow[2 * j + 1]; }
                if (FLAGS & F_RELU) { v0 = fmaxf(v0, 0.f); v1 = fmaxf(v1, 0.f); }
                if (FLAGS & F_RES)  { v0 += rrow[2 * j];  v1 += rrow[2 * j + 1]; }
                *reinterpret_cast<float2*>(&orow[2 * j]) = make_float2(v0, v1);
            }
        }
    }
}

// ---------------- GCN aggregation: one warp per dst node ----------------
__global__ void k_agg(const float* __restrict__ xw, const float* __restrict__ bias,
                      float* __restrict__ out)
{
    int warp = (blockIdx.x * blockDim.x + threadIdx.x) >> 5;
    int lane = threadIdx.x & 31;
    if (warp >= NNODES) return;
    int v = warp;
    int s = g_row_ptr[v], e = g_row_ptr[v + 1];
    float a0 = 0.f, a1 = 0.f, a2 = 0.f;
    for (int i = s; i < e; i++) {
        int u = g_csr_src[i];
        float wn = g_dis[u];
        const float* r = xw + (size_t)u * HDIM;
        a0 += wn * r[lane];
        a1 += wn * r[lane + 32];
        a2 += wn * r[lane + 64];
    }
    float dv = g_dis[v];
    float iv = g_invdeg[v];
    const float* sr = xw + (size_t)v * HDIM;
    float* o = out + (size_t)v * HDIM;
    o[lane]      = a0 * dv + sr[lane]      * iv + bias[lane];
    o[lane + 32] = a1 * dv + sr[lane + 32] * iv + bias[lane + 32];
    o[lane + 64] = a2 * dv + sr[lane + 64] * iv + bias[lane + 64];
}

// ---------------- launch ----------------
extern "C" void kernel_launch(void* const* d_in, const int* in_sizes, int n_in,
                              void* d_out, int out_size)
{
    const float* x       = (const float*)d_in[0];
    const int*   t       = (const int*)  d_in[1];
    const int*   ei      = (const int*)  d_in[2];
    const float* emb     = (const float*)d_in[3];
    const float* fw_W    = (const float*)d_in[4];
    const float* fw_b    = (const float*)d_in[5];
    const float* pre_W   = (const float*)d_in[6];
    const float* pre_b   = (const float*)d_in[7];
    const float* conv_W  = (const float*)d_in[8];
    const float* conv_b  = (const float*)d_in[9];
    const float* post_W1 = (const float*)d_in[10];
    const float* post_b1 = (const float*)d_in[11];
    const float* post_W2 = (const float*)d_in[12];
    const float* post_b2 = (const float*)d_in[13];
    const float* fin_W   = (const float*)d_in[14];
    const float* fin_b   = (const float*)d_in[15];
    float* out = (float*)d_out;

    const int* src = ei;
    const int* dst = ei + NEDGES;

    float *A, *B, *C, *D, *Wc, *bc;
    cudaGetSymbolAddress((void**)&A,  g_bufA);
    cudaGetSymbolAddress((void**)&B,  g_bufB);
    cudaGetSymbolAddress((void**)&C,  g_bufC);
    cudaGetSymbolAddress((void**)&D,  g_bufD);
    cudaGetSymbolAddress((void**)&Wc, g_Wc);
    cudaGetSymbolAddress((void**)&bc, g_bc);

    const int SMEM96 = (128 * 100 + 96 * 96) * 4;
    const int SMEM32 = (128 * 100 + 96 * 32) * 4;
    cudaFuncSetAttribute(k_gemm<96, F_BIAS>,          cudaFuncAttributeMaxDynamicSharedMemorySize, SMEM96);
    cudaFuncSetAttribute(k_gemm<96, F_BIAS | F_RELU>, cudaFuncAttributeMaxDynamicSharedMemorySize, SMEM96);
    cudaFuncSetAttribute(k_gemm<96, F_BIAS | F_RES>,  cudaFuncAttributeMaxDynamicSharedMemorySize, SMEM96);
    cudaFuncSetAttribute(k_gemm<32, F_BIAS>,          cudaFuncAttributeMaxDynamicSharedMemorySize, SMEM32);

    // graph build
    k_zero_deg  <<<(NNODES + 255) / 256, 256>>>();
    k_hist      <<<(NEDGES + 255) / 256, 256>>>(dst);
    k_scan_part <<<SCAN_NBLK, SCAN_B>>>();
    k_scan_mid  <<<1, 1>>>();
    k_scan_apply<<<SCAN_NBLK, SCAN_B>>>();
    k_scatter   <<<(NEDGES + 255) / 256, 256>>>(src, dst);

    const int GG = (NNODES + 127) / 128;
    const int AGG_BLOCKS = (NNODES * 32 + 255) / 256;

    // first layer
    k_gemm<96, F_BIAS><<<GG, 256, SMEM96>>>(x, fw_W, fw_b, nullptr, A, NNODES);

    for (int l = 0; l < 2; l++) {
        const float* pW = pre_W   + l * HDIM * HDIM;
        const float* pb = pre_b   + l * HDIM;
        const float* cW = conv_W  + l * HDIM * HDIM;
        const float* cb = conv_b  + l * HDIM;
        const float* w1 = post_W1 + l * HDIM * HDIM;
        const float* b1 = post_b1 + l * HDIM;
        const float* w2 = post_W2 + l * HDIM * HDIM;
        const float* b2 = post_b2 + l * HDIM;

        // Wc = convW @ preW ; bc = convW @ (pre_b + emb[t])
        k_compose<<<HDIM, HDIM>>>(pW, pb, cW, emb, t);
        // C = A @ Wc^T + bc   (fused pre_mlp + conv linear)
        k_gemm<96, F_BIAS><<<GG, 256, SMEM96>>>(A, Wc, bc, nullptr, C, NNODES);
        // D = GCN aggregate(C) + conv_b
        k_agg<<<AGG_BLOCKS, 256>>>(C, cb, D);
        // B = relu(D @ W1^T + b1)
        k_gemm<96, F_BIAS | F_RELU><<<GG, 256, SMEM96>>>(D, w1, b1, nullptr, B, NNODES);
        // C = B @ W2^T + b2 + A
        k_gemm<96, F_BIAS | F_RES><<<GG, 256, SMEM96>>>(B, w2, b2, A, C, NNODES);
        float* tmp = A; A = C; C = tmp;
    }

    k_gemm<32, F_BIAS><<<GG, 256, SMEM32>>>(A, fin_W, fin_b, nullptr, out, NNODES);
}

// round 4
// speedup vs baseline: 3.0000x; 1.7394x over previous
#include <cuda_runtime.h>
#include <cuda_bf16.h>
#include <cstdint>

#define NNODES 50000
#define NEDGES 800000
#define HDIM   96

typedef unsigned long long u64;
typedef unsigned int u32;

// ---------------- scratch ----------------
__device__ __align__(128) float g_bufA[NNODES * HDIM];
__device__ __align__(128) float g_bufB[NNODES * HDIM];
__device__ __align__(128) float g_bufC[NNODES * HDIM];
__device__ __align__(128) float g_bufD[NNODES * HDIM];
__device__ __align__(128) float g_Wc[HDIM * HDIM];
__device__ __align__(128) float g_bc[HDIM];
__device__ int   g_deg[NNODES];
__device__ float g_dis[NNODES];
__device__ float g_invdeg[NNODES];
__device__ int   g_row_ptr[NNODES + 1];
__device__ int   g_cursor[NNODES];
__device__ int   g_csr_src[NEDGES];
__device__ int   g_part[128];

// ---------------- graph build ----------------
__global__ void k_zero_deg() {
    int i = blockIdx.x * blockDim.x + threadIdx.x;
    if (i < NNODES) g_deg[i] = 0;
}
__global__ void k_hist(const int* __restrict__ dst) {
    int i = blockIdx.x * blockDim.x + threadIdx.x;
    if (i < NEDGES) atomicAdd(&g_deg[dst[i]], 1);
}

#define SCAN_B 512
#define SCAN_NBLK ((NNODES + SCAN_B - 1) / SCAN_B)

__global__ void k_scan_part() {
    __shared__ int ws[16];
    int i = blockIdx.x * SCAN_B + threadIdx.x;
    int v = (i < NNODES) ? g_deg[i] : 0;
    int lane = threadIdx.x & 31, wid = threadIdx.x >> 5;
    int s = v;
    #pragma unroll
    for (int o = 16; o > 0; o >>= 1) s += __shfl_down_sync(0xffffffffu, s, o);
    if (lane == 0) ws[wid] = s;
    __syncthreads();
    if (wid == 0) {
        int t = (lane < (SCAN_B / 32)) ? ws[lane] : 0;
        #pragma unroll
        for (int o = 16; o > 0; o >>= 1) t += __shfl_down_sync(0xffffffffu, t, o);
        if (lane == 0) g_part[blockIdx.x] = t;
    }
}
__global__ void k_scan_mid() {
    int acc = 0;
    for (int j = 0; j < SCAN_NBLK; j++) { int t = g_part[j]; g_part[j] = acc; acc += t; }
    g_row_ptr[NNODES] = acc;
}
__global__ void k_scan_apply() {
    __shared__ int ws[17];
    int i = blockIdx.x * SCAN_B + threadIdx.x;
    int v = (i < NNODES) ? g_deg[i] : 0;
    int lane = threadIdx.x & 31, wid = threadIdx.x >> 5;
    int x = v;
    #pragma unroll
    for (int o = 1; o < 32; o <<= 1) {
        int y = __shfl_up_sync(0xffffffffu, x, o);
        if (lane >= o) x += y;
    }
    if (lane == 31) ws[wid] = x;
    __syncthreads();
    if (wid == 0) {
        int nw = SCAN_B / 32;
        int s = (lane < nw) ? ws[lane] : 0;
        #pragma unroll
        for (int o = 1; o < 32; o <<= 1) {
            int y = __shfl_up_sync(0xffffffffu, s, o);
            if (lane >= o) s += y;
        }
        if (lane < nw) ws[lane] = s;
    }
    __syncthreads();
    int excl = x - v + (wid > 0 ? ws[wid - 1] : 0) + g_part[blockIdx.x];
    if (i < NNODES) {
        g_row_ptr[i] = excl;
        g_cursor[i] = excl;
        float d = (float)(v + 1);
        g_dis[i] = rsqrtf(d);
        g_invdeg[i] = 1.0f / d;
    }
}
__global__ void k_scatter(const int* __restrict__ src, const int* __restrict__ dst) {
    int i = blockIdx.x * blockDim.x + threadIdx.x;
    if (i < NEDGES) {
        int d = dst[i];
        int p = atomicAdd(&g_cursor[d], 1);
        g_csr_src[p] = src[i];
    }
}

// ---------------- weight compose: Wc = convW @ preW ; bc = convW @ (pre_b + emb[t]) ----
__global__ void k_compose(const float* __restrict__ preW, const float* __restrict__ pre_b,
                          const float* __restrict__ convW,
                          const float* __restrict__ emb, const int* __restrict__ t)
{
    __shared__ float cw[HDIM];
    __shared__ float red[HDIM];
    int j = blockIdx.x, k = threadIdx.x;
    cw[k] = convW[j * HDIM + k];
    __syncthreads();
    float acc = 0.f;
    #pragma unroll 4
    for (int m = 0; m < HDIM; m++) acc += cw[m] * preW[m * HDIM + k];
    g_Wc[j * HDIM + k] = acc;
    int t0 = t[0];
    red[k] = cw[k] * (pre_b[k] + emb[t0 * HDIM + k]);
    __syncthreads();
    if (k == 0) {
        float s = 0.f;
        for (int m = 0; m < HDIM; m++) s += red[m];
        g_bc[j] = s;
    }
}

// ---------------- mma.sync bf16-split GEMM ----------------
// out[N,HOUT] = in[N,96] @ W[HOUT,96]^T (+ bias/relu/res)
// 2-term bf16 split: D = Xh*Wh + Xh*Wl + Xl*Wh  (residual ~2^-17)
enum { F_BIAS = 1, F_RELU = 4, F_RES = 8 };

__device__ __forceinline__ void mma16816(float* c, const u32* a, const u32* b) {
    asm volatile(
        "mma.sync.aligned.m16n8k16.row.col.f32.bf16.bf16.f32 "
        "{%0,%1,%2,%3}, {%4,%5,%6,%7}, {%8,%9}, {%0,%1,%2,%3};"
        : "+f"(c[0]), "+f"(c[1]), "+f"(c[2]), "+f"(c[3])
        : "r"(a[0]), "r"(a[1]), "r"(a[2]), "r"(a[3]), "r"(b[0]), "r"(b[1]));
}

__device__ __forceinline__ u32 pack_hi(float f0, float f1) {
    __nv_bfloat162 p;
    p.x = __float2bfloat16(f0);
    p.y = __float2bfloat16(f1);
    return *reinterpret_cast<u32*>(&p);
}
__device__ __forceinline__ u32 pack_lo(float f0, float f1) {
    __nv_bfloat162 p;
    __nv_bfloat16 h0 = __float2bfloat16(f0), h1 = __float2bfloat16(f1);
    p.x = __float2bfloat16(f0 - __bfloat162float(h0));
    p.y = __float2bfloat16(f1 - __bfloat162float(h1));
    return *reinterpret_cast<u32*>(&p);
}

template <int HOUT, unsigned FLAGS>
__global__ void __launch_bounds__(256) k_mma(
    const float* __restrict__ in, const float* __restrict__ W,
    const float* __restrict__ bias, const float* __restrict__ res,
    float* __restrict__ out, int nrows)
{
    // smem: padded bf16 tiles, row stride 208 B (52 words -> conflict-free frag loads)
    const int STR = 208;
    const int NT = HOUT / 8;
    const int SM_XH = 0;
    const int SM_XL = 128 * STR;            // 26624
    const int SM_WH = 2 * 128 * STR;        // 53248
    const int SM_WL = SM_WH + HOUT * STR;
    extern __shared__ char sm[];

    int tid = threadIdx.x;
    int r0 = blockIdx.x * 128;

    // --- stage X (128 rows x 96) as hi/lo bf16 ---
    for (int i = tid; i < 128 * 12; i += 256) {
        int row = i / 12, col = (i - row * 12) * 8;
        if (r0 + row < nrows) {
            const float4* p = reinterpret_cast<const float4*>(in + (size_t)(r0 + row) * HDIM + col);
            float4 v0 = p[0], v1 = p[1];
            float xs[8] = {v0.x, v0.y, v0.z, v0.w, v1.x, v1.y, v1.z, v1.w};
            uint4 hw, lw;
            hw.x = pack_hi(xs[0], xs[1]); hw.y = pack_hi(xs[2], xs[3]);
            hw.z = pack_hi(xs[4], xs[5]); hw.w = pack_hi(xs[6], xs[7]);
            lw.x = pack_lo(xs[0], xs[1]); lw.y = pack_lo(xs[2], xs[3]);
            lw.z = pack_lo(xs[4], xs[5]); lw.w = pack_lo(xs[6], xs[7]);
            *reinterpret_cast<uint4*>(sm + SM_XH + row * STR + col * 2) = hw;
            *reinterpret_cast<uint4*>(sm + SM_XL + row * STR + col * 2) = lw;
        }
    }
    // --- stage W (HOUT rows x 96) as hi/lo bf16 ---
    for (int i = tid; i < HOUT * 12; i += 256) {
        int row = i / 12, col = (i - row * 12) * 8;
        const float4* p = reinterpret_cast<const float4*>(W + (size_t)row * HDIM + col);
        float4 v0 = p[0], v1 = p[1];
        float xs[8] = {v0.x, v0.y, v0.z, v0.w, v1.x, v1.y, v1.z, v1.w};
        uint4 hw, lw;
        hw.x = pack_hi(xs[0], xs[1]); hw.y = pack_hi(xs[2], xs[3]);
        hw.z = pack_hi(xs[4], xs[5]); hw.w = pack_hi(xs[6], xs[7]);
        lw.x = pack_lo(xs[0], xs[1]); lw.y = pack_lo(xs[2], xs[3]);
        lw.z = pack_lo(xs[4], xs[5]); lw.w = pack_lo(xs[6], xs[7]);
        *reinterpret_cast<uint4*>(sm + SM_WH + row * STR + col * 2) = hw;
        *reinterpret_cast<uint4*>(sm + SM_WL + row * STR + col * 2) = lw;
    }
    __syncthreads();

    int w = tid >> 5, lane = tid & 31;
    int g = lane >> 2, tg = lane & 3;

    float acc[NT][4];
    #pragma unroll
    for (int nt = 0; nt < NT; nt++)
        #pragma unroll
        for (int j = 0; j < 4; j++) acc[nt][j] = 0.f;

    const char* xh = sm + SM_XH + (w * 16 + g) * STR;
    const char* xl = sm + SM_XL + (w * 16 + g) * STR;

    #pragma unroll
    for (int kc = 0; kc < 6; kc++) {
        int o0 = (kc * 16 + 2 * tg) * 2;   // byte offset of k-pair
        int o8 = o0 + 16;                  // +8 k
        u32 ah[4], al[4];
        ah[0] = *reinterpret_cast<const u32*>(xh + o0);
        ah[1] = *reinterpret_cast<const u32*>(xh + 8 * STR + o0);
        ah[2] = *reinterpret_cast<const u32*>(xh + o8);
        ah[3] = *reinterpret_cast<const u32*>(xh + 8 * STR + o8);
        al[0] = *reinterpret_cast<const u32*>(xl + o0);
        al[1] = *reinterpret_cast<const u32*>(xl + 8 * STR + o0);
        al[2] = *reinterpret_cast<const u32*>(xl + o8);
        al[3] = *reinterpret_cast<const u32*>(xl + 8 * STR + o8);

        #pragma unroll
        for (int nt = 0; nt < NT; nt++) {
            const char* wh = sm + SM_WH + (nt * 8 + g) * STR;
            const char* wl = sm + SM_WL + (nt * 8 + g) * STR;
            u32 bh[2], bl[2];
            bh[0] = *reinterpret_cast<const u32*>(wh + o0);
            bh[1] = *reinterpret_cast<const u32*>(wh + o8);
            bl[0] = *reinterpret_cast<const u32*>(wl + o0);
            bl[1] = *reinterpret_cast<const u32*>(wl + o8);
            mma16816(acc[nt], ah, bh);
            mma16816(acc[nt], ah, bl);
            mma16816(acc[nt], al, bh);
        }
    }

    // --- epilogue ---
    int row0 = r0 + w * 16 + g;
    int row1 = row0 + 8;
    #pragma unroll
    for (int nt = 0; nt < NT; nt++) {
        int n0 = nt * 8 + 2 * tg;
        float2 bv = make_float2(0.f, 0.f);
        if (FLAGS & F_BIAS) bv = *reinterpret_cast<const float2*>(bias + n0);
        if (row0 < nrows) {
            float v0 = acc[nt][0] + bv.x, v1 = acc[nt][1] + bv.y;
            if (FLAGS & F_RELU) { v0 = fmaxf(v0, 0.f); v1 = fmaxf(v1, 0.f); }
            if (FLAGS & F_RES) {
                float2 rv = *reinterpret_cast<const float2*>(res + (size_t)row0 * HOUT + n0);
                v0 += rv.x; v1 += rv.y;
            }
            *reinterpret_cast<float2*>(out + (size_t)row0 * HOUT + n0) = make_float2(v0, v1);
        }
        if (row1 < nrows) {
            float v0 = acc[nt][2] + bv.x, v1 = acc[nt][3] + bv.y;
            if (FLAGS & F_RELU) { v0 = fmaxf(v0, 0.f); v1 = fmaxf(v1, 0.f); }
            if (FLAGS & F_RES) {
                float2 rv = *reinterpret_cast<const float2*>(res + (size_t)row1 * HOUT + n0);
                v0 += rv.x; v1 += rv.y;
            }
            *reinterpret_cast<float2*>(out + (size_t)row1 * HOUT + n0) = make_float2(v0, v1);
        }
    }
}

// ---------------- GCN aggregation: one warp per dst node ----------------
__global__ void k_agg(const float* __restrict__ xw, const float* __restrict__ bias,
                      float* __restrict__ out)
{
    int warp = (blockIdx.x * blockDim.x + threadIdx.x) >> 5;
    int lane = threadIdx.x & 31;
    if (warp >= NNODES) return;
    int v = warp;
    int s = g_row_ptr[v], e = g_row_ptr[v + 1];
    float a0 = 0.f, a1 = 0.f, a2 = 0.f;
    for (int i = s; i < e; i++) {
        int u = g_csr_src[i];
        float wn = g_dis[u];
        const float* r = xw + (size_t)u * HDIM;
        a0 += wn * r[lane];
        a1 += wn * r[lane + 32];
        a2 += wn * r[lane + 64];
    }
    float dv = g_dis[v];
    float iv = g_invdeg[v];
    const float* sr = xw + (size_t)v * HDIM;
    float* o = out + (size_t)v * HDIM;
    o[lane]      = a0 * dv + sr[lane]      * iv + bias[lane];
    o[lane + 32] = a1 * dv + sr[lane + 32] * iv + bias[lane + 32];
    o[lane + 64] = a2 * dv + sr[lane + 64] * iv + bias[lane + 64];
}

// ---------------- launch ----------------
extern "C" void kernel_launch(void* const* d_in, const int* in_sizes, int n_in,
                              void* d_out, int out_size)
{
    const float* x       = (const float*)d_in[0];
    const int*   t       = (const int*)  d_in[1];
    const int*   ei      = (const int*)  d_in[2];
    const float* emb     = (const float*)d_in[3];
    const float* fw_W    = (const float*)d_in[4];
    const float* fw_b    = (const float*)d_in[5];
    const float* pre_W   = (const float*)d_in[6];
    const float* pre_b   = (const float*)d_in[7];
    const float* conv_W  = (const float*)d_in[8];
    const float* conv_b  = (const float*)d_in[9];
    const float* post_W1 = (const float*)d_in[10];
    const float* post_b1 = (const float*)d_in[11];
    const float* post_W2 = (const float*)d_in[12];
    const float* post_b2 = (const float*)d_in[13];
    const float* fin_W   = (const float*)d_in[14];
    const float* fin_b   = (const float*)d_in[15];
    float* out = (float*)d_out;

    const int* src = ei;
    const int* dst = ei + NEDGES;

    float *A, *B, *C, *D, *Wc, *bc;
    cudaGetSymbolAddress((void**)&A,  g_bufA);
    cudaGetSymbolAddress((void**)&B,  g_bufB);
    cudaGetSymbolAddress((void**)&C,  g_bufC);
    cudaGetSymbolAddress((void**)&D,  g_bufD);
    cudaGetSymbolAddress((void**)&Wc, g_Wc);
    cudaGetSymbolAddress((void**)&bc, g_bc);

    const int SMEM96 = 2 * 128 * 208 + 2 * 96 * 208;   // 93184
    const int SMEM32 = 2 * 128 * 208 + 2 * 32 * 208;   // 66560
    cudaFuncSetAttribute(k_mma<96, F_BIAS>,          cudaFuncAttributeMaxDynamicSharedMemorySize, SMEM96);
    cudaFuncSetAttribute(k_mma<96, F_BIAS | F_RELU>, cudaFuncAttributeMaxDynamicSharedMemorySize, SMEM96);
    cudaFuncSetAttribute(k_mma<96, F_BIAS | F_RES>,  cudaFuncAttributeMaxDynamicSharedMemorySize, SMEM96);
    cudaFuncSetAttribute(k_mma<32, F_BIAS>,          cudaFuncAttributeMaxDynamicSharedMemorySize, SMEM32);

    // graph build
    k_zero_deg  <<<(NNODES + 255) / 256, 256>>>();
    k_hist      <<<(NEDGES + 255) / 256, 256>>>(dst);
    k_scan_part <<<SCAN_NBLK, SCAN_B>>>();
    k_scan_mid  <<<1, 1>>>();
    k_scan_apply<<<SCAN_NBLK, SCAN_B>>>();
    k_scatter   <<<(NEDGES + 255) / 256, 256>>>(src, dst);

    const int GG = (NNODES + 127) / 128;
    const int AGG_BLOCKS = (NNODES * 32 + 255) / 256;

    // first layer: A = x @ fw_W^T + fw_b
    k_mma<96, F_BIAS><<<GG, 256, SMEM96>>>(x, fw_W, fw_b, nullptr, A, NNODES);

    for (int l = 0; l < 2; l++) {
        const float* pW = pre_W   + l * HDIM * HDIM;
        const float* pb = pre_b   + l * HDIM;
        const float* cW = conv_W  + l * HDIM * HDIM;
        const float* cb = conv_b  + l * HDIM;
        const float* w1 = post_W1 + l * HDIM * HDIM;
        const float* b1 = post_b1 + l * HDIM;
        const float* w2 = post_W2 + l * HDIM * HDIM;
        const float* b2 = post_b2 + l * HDIM;

        k_compose<<<HDIM, HDIM>>>(pW, pb, cW, emb, t);
        // C = A @ Wc^T + bc   (fused pre_mlp + conv linear)
        k_mma<96, F_BIAS><<<GG, 256, SMEM96>>>(A, Wc, bc, nullptr, C, NNODES);
        // D = GCN aggregate(C) + conv_b
        k_agg<<<AGG_BLOCKS, 256>>>(C, cb, D);
        // B = relu(D @ W1^T + b1)
        k_mma<96, F_BIAS | F_RELU><<<GG, 256, SMEM96>>>(D, w1, b1, nullptr, B, NNODES);
        // C = B @ W2^T + b2 + A
        k_mma<96, F_BIAS | F_RES><<<GG, 256, SMEM96>>>(B, w2, b2, A, C, NNODES);
        float* tmp = A; A = C; C = tmp;
    }

    k_mma<32, F_BIAS><<<GG, 256, SMEM32>>>(A, fin_W, fin_b, nullptr, out, NNODES);
}

// round 5
// speedup vs baseline: 3.0967x; 1.0322x over previous
#include <cuda_runtime.h>
#include <cuda_bf16.h>
#include <cstdint>

#define NNODES 50000
#define NEDGES 800000
#define HDIM   96

typedef unsigned long long u64;
typedef unsigned int u32;

// ---------------- scratch ----------------
__device__ __align__(128) float g_bufA[NNODES * HDIM];
__device__ __align__(128) float g_bufB[NNODES * HDIM];
__device__ __align__(128) float g_bufC[NNODES * HDIM];
__device__ __align__(128) float g_bufD[NNODES * HDIM];
__device__ __align__(128) float g_Wc[2][HDIM * HDIM];
__device__ __align__(128) float g_bc[2][HDIM];
__device__ int   g_deg[NNODES];
__device__ float g_dis[NNODES];
__device__ float g_invdeg[NNODES];
__device__ int   g_row_ptr[NNODES + 1];
__device__ int   g_cursor[NNODES];
__device__ int   g_csr_src[NEDGES];
__device__ int   g_part[128];

// ---------------- graph build ----------------
__global__ void k_zero_deg() {
    int i = blockIdx.x * blockDim.x + threadIdx.x;
    if (i < NNODES) g_deg[i] = 0;
}
__global__ void k_hist(const int* __restrict__ dst) {
    int i = blockIdx.x * blockDim.x + threadIdx.x;
    if (i < NEDGES) atomicAdd(&g_deg[dst[i]], 1);
}

#define SCAN_B 512
#define SCAN_NBLK ((NNODES + SCAN_B - 1) / SCAN_B)

__global__ void k_scan_part() {
    __shared__ int ws[16];
    int i = blockIdx.x * SCAN_B + threadIdx.x;
    int v = (i < NNODES) ? g_deg[i] : 0;
    int lane = threadIdx.x & 31, wid = threadIdx.x >> 5;
    int s = v;
    #pragma unroll
    for (int o = 16; o > 0; o >>= 1) s += __shfl_down_sync(0xffffffffu, s, o);
    if (lane == 0) ws[wid] = s;
    __syncthreads();
    if (wid == 0) {
        int t = (lane < (SCAN_B / 32)) ? ws[lane] : 0;
        #pragma unroll
        for (int o = 16; o > 0; o >>= 1) t += __shfl_down_sync(0xffffffffu, t, o);
        if (lane == 0) g_part[blockIdx.x] = t;
    }
}
__global__ void k_scan_mid() {           // 1 warp, shfl scan over SCAN_NBLK partials
    int lane = threadIdx.x;
    int carry = 0;
    for (int base = 0; base < SCAN_NBLK; base += 32) {
        int i = base + lane;
        int v = (i < SCAN_NBLK) ? g_part[i] : 0;
        int x = v;
        #pragma unroll
        for (int o = 1; o < 32; o <<= 1) {
            int y = __shfl_up_sync(0xffffffffu, x, o);
            if (lane >= o) x += y;
        }
        if (i < SCAN_NBLK) g_part[i] = carry + x - v;
        carry += __shfl_sync(0xffffffffu, x, 31);
    }
    if (lane == 0) g_row_ptr[NNODES] = carry;
}
__global__ void k_scan_apply() {
    __shared__ int ws[17];
    int i = blockIdx.x * SCAN_B + threadIdx.x;
    int v = (i < NNODES) ? g_deg[i] : 0;
    int lane = threadIdx.x & 31, wid = threadIdx.x >> 5;
    int x = v;
    #pragma unroll
    for (int o = 1; o < 32; o <<= 1) {
        int y = __shfl_up_sync(0xffffffffu, x, o);
        if (lane >= o) x += y;
    }
    if (lane == 31) ws[wid] = x;
    __syncthreads();
    if (wid == 0) {
        int nw = SCAN_B / 32;
        int s = (lane < nw) ? ws[lane] : 0;
        #pragma unroll
        for (int o = 1; o < 32; o <<= 1) {
            int y = __shfl_up_sync(0xffffffffu, s, o);
            if (lane >= o) s += y;
        }
        if (lane < nw) ws[lane] = s;
    }
    __syncthreads();
    int excl = x - v + (wid > 0 ? ws[wid - 1] : 0) + g_part[blockIdx.x];
    if (i < NNODES) {
        g_row_ptr[i] = excl;
        g_cursor[i] = excl;
        float d = (float)(v + 1);
        g_dis[i] = rsqrtf(d);
        g_invdeg[i] = 1.0f / d;
    }
}
__global__ void k_scatter(const int* __restrict__ src, const int* __restrict__ dst) {
    int i = blockIdx.x * blockDim.x + threadIdx.x;
    if (i < NEDGES) {
        int d = dst[i];
        int p = atomicAdd(&g_cursor[d], 1);
        g_csr_src[p] = src[i];
    }
}

// ---------------- weight compose: Wc = convW @ preW ; bc = convW @ (pre_b + emb[t]) ----
__global__ void k_compose(const float* __restrict__ preW, const float* __restrict__ pre_b,
                          const float* __restrict__ convW,
                          const float* __restrict__ emb, const int* __restrict__ t,
                          float* __restrict__ Wc, float* __restrict__ bc)
{
    __shared__ float cw[HDIM];
    __shared__ float red[HDIM];
    int j = blockIdx.x, k = threadIdx.x;
    cw[k] = convW[j * HDIM + k];
    __syncthreads();
    float acc = 0.f;
    #pragma unroll 4
    for (int m = 0; m < HDIM; m++) acc += cw[m] * preW[m * HDIM + k];
    Wc[j * HDIM + k] = acc;
    int t0 = t[0];
    red[k] = cw[k] * (pre_b[k] + emb[t0 * HDIM + k]);
    __syncthreads();
    if (k == 0) {
        float s = 0.f;
        for (int m = 0; m < HDIM; m++) s += red[m];
        bc[j] = s;
    }
}

// ---------------- mma.sync bf16-split GEMM pieces ----------------
enum { F_BIAS = 1, F_RELU = 4, F_RES = 8 };

__device__ __forceinline__ void mma16816(float* c, const u32* a, const u32* b) {
    asm volatile(
        "mma.sync.aligned.m16n8k16.row.col.f32.bf16.bf16.f32 "
        "{%0,%1,%2,%3}, {%4,%5,%6,%7}, {%8,%9}, {%0,%1,%2,%3};"
        : "+f"(c[0]), "+f"(c[1]), "+f"(c[2]), "+f"(c[3])
        : "r"(a[0]), "r"(a[1]), "r"(a[2]), "r"(a[3]), "r"(b[0]), "r"(b[1]));
}
__device__ __forceinline__ u32 pack_hi(float f0, float f1) {
    __nv_bfloat162 p;
    p.x = __float2bfloat16(f0);
    p.y = __float2bfloat16(f1);
    return *reinterpret_cast<u32*>(&p);
}
__device__ __forceinline__ u32 pack_lo(float f0, float f1) {
    __nv_bfloat162 p;
    __nv_bfloat16 h0 = __float2bfloat16(f0), h1 = __float2bfloat16(f1);
    p.x = __float2bfloat16(f0 - __bfloat162float(h0));
    p.y = __float2bfloat16(f1 - __bfloat162float(h1));
    return *reinterpret_cast<u32*>(&p);
}

#define STR 208   // smem row stride (bytes): 52 words -> conflict-free frag loads

// stage a [rows x 96] fp32 matrix as hi/lo bf16 tiles
__device__ __forceinline__ void stage_hi_lo(
    const float* __restrict__ src, char* smh, char* sml,
    int rows, int r0, int nrows, int tid, int nthr)
{
    for (int i = tid; i < rows * 12; i += nthr) {
        int row = i / 12, col = (i - row * 12) * 8;
        if (r0 + row < nrows) {
            const float4* p = reinterpret_cast<const float4*>(src + (size_t)(r0 + row) * HDIM + col);
            float4 v0 = p[0], v1 = p[1];
            float xs[8] = {v0.x, v0.y, v0.z, v0.w, v1.x, v1.y, v1.z, v1.w};
            uint4 hw, lw;
            hw.x = pack_hi(xs[0], xs[1]); hw.y = pack_hi(xs[2], xs[3]);
            hw.z = pack_hi(xs[4], xs[5]); hw.w = pack_hi(xs[6], xs[7]);
            lw.x = pack_lo(xs[0], xs[1]); lw.y = pack_lo(xs[2], xs[3]);
            lw.z = pack_lo(xs[4], xs[5]); lw.w = pack_lo(xs[6], xs[7]);
            *reinterpret_cast<uint4*>(smh + row * STR + col * 2) = hw;
            *reinterpret_cast<uint4*>(sml + row * STR + col * 2) = lw;
        }
    }
}

// compute 3-term split MMA over K=96 for this warp's 16-row stripe
template <int NT>
__device__ __forceinline__ void mma_pass(
    const char* xh, const char* xl, const char* wmh, const char* wml,
    int g, int tg, float acc[][4])
{
    #pragma unroll
    for (int kc = 0; kc < 6; kc++) {
        int o0 = (kc * 16 + 2 * tg) * 2;
        int o8 = o0 + 16;
        u32 ah[4], al[4];
        ah[0] = *reinterpret_cast<const u32*>(xh + o0);
        ah[1] = *reinterpret_cast<const u32*>(xh + 8 * STR + o0);
        ah[2] = *reinterpret_cast<const u32*>(xh + o8);
        ah[3] = *reinterpret_cast<const u32*>(xh + 8 * STR + o8);
        al[0] = *reinterpret_cast<const u32*>(xl + o0);
        al[1] = *reinterpret_cast<const u32*>(xl + 8 * STR + o0);
        al[2] = *reinterpret_cast<const u32*>(xl + o8);
        al[3] = *reinterpret_cast<const u32*>(xl + 8 * STR + o8);
        #pragma unroll
        for (int nt = 0; nt < NT; nt++) {
            const char* wh = wmh + (nt * 8 + g) * STR;
            const char* wl = wml + (nt * 8 + g) * STR;
            u32 bh[2], bl[2];
            bh[0] = *reinterpret_cast<const u32*>(wh + o0);
            bh[1] = *reinterpret_cast<const u32*>(wh + o8);
            bl[0] = *reinterpret_cast<const u32*>(wl + o0);
            bl[1] = *reinterpret_cast<const u32*>(wl + o8);
            mma16816(acc[nt], ah, bh);
            mma16816(acc[nt], ah, bl);
            mma16816(acc[nt], al, bh);
        }
    }
}

// ---------------- single GEMM kernel ----------------
template <int HOUT, unsigned FLAGS>
__global__ void __launch_bounds__(256) k_mma(
    const float* __restrict__ in, const float* __restrict__ W,
    const float* __restrict__ bias, const float* __restrict__ res,
    float* __restrict__ out, int nrows)
{
    const int NT = HOUT / 8;
    const int SM_XH = 0, SM_XL = 128 * STR;
    const int SM_WH = 2 * 128 * STR, SM_WL = SM_WH + HOUT * STR;
    extern __shared__ char sm[];
    int tid = threadIdx.x;
    int r0 = blockIdx.x * 128;

    stage_hi_lo(in, sm + SM_XH, sm + SM_XL, 128, r0, nrows, tid, 256);
    stage_hi_lo(W,  sm + SM_WH, sm + SM_WL, HOUT, 0, HOUT, tid, 256);
    __syncthreads();

    int w = tid >> 5, lane = tid & 31;
    int g = lane >> 2, tg = lane & 3;

    float acc[NT][4];
    #pragma unroll
    for (int nt = 0; nt < NT; nt++) { acc[nt][0] = acc[nt][1] = acc[nt][2] = acc[nt][3] = 0.f; }

    mma_pass<NT>(sm + SM_XH + (w * 16 + g) * STR, sm + SM_XL + (w * 16 + g) * STR,
                 sm + SM_WH, sm + SM_WL, g, tg, acc);

    int row0 = r0 + w * 16 + g, row1 = row0 + 8;
    #pragma unroll
    for (int nt = 0; nt < NT; nt++) {
        int n0 = nt * 8 + 2 * tg;
        float2 bv = make_float2(0.f, 0.f);
        if (FLAGS & F_BIAS) bv = *reinterpret_cast<const float2*>(bias + n0);
        if (row0 < nrows) {
            float v0 = acc[nt][0] + bv.x, v1 = acc[nt][1] + bv.y;
            if (FLAGS & F_RELU) { v0 = fmaxf(v0, 0.f); v1 = fmaxf(v1, 0.f); }
            if (FLAGS & F_RES) {
                float2 rv = *reinterpret_cast<const float2*>(res + (size_t)row0 * HOUT + n0);
                v0 += rv.x; v1 += rv.y;
            }
            *reinterpret_cast<float2*>(out + (size_t)row0 * HOUT + n0) = make_float2(v0, v1);
        }
        if (row1 < nrows) {
            float v0 = acc[nt][2] + bv.x, v1 = acc[nt][3] + bv.y;
            if (FLAGS & F_RELU) { v0 = fmaxf(v0, 0.f); v1 = fmaxf(v1, 0.f); }
            if (FLAGS & F_RES) {
                float2 rv = *reinterpret_cast<const float2*>(res + (size_t)row1 * HOUT + n0);
                v0 += rv.x; v1 += rv.y;
            }
            *reinterpret_cast<float2*>(out + (size_t)row1 * HOUT + n0) = make_float2(v0, v1);
        }
    }
}

// ---------------- fused post-MLP: out = relu(in@W1^T+b1)@W2^T + b2 + res ----------------
__global__ void __launch_bounds__(256) k_mma2(
    const float* __restrict__ in,
    const float* __restrict__ W1, const float* __restrict__ b1,
    const float* __restrict__ W2, const float* __restrict__ b2,
    const float* __restrict__ res, float* __restrict__ out, int nrows)
{
    const int NT = 12;
    const int SM_XH  = 0, SM_XL = 128 * STR;               // 0, 26624
    const int SM_W1H = 2 * 128 * STR;                      // 53248
    const int SM_W1L = SM_W1H + 96 * STR;                  // 73216
    const int SM_W2H = SM_W1L + 96 * STR;                  // 93184
    const int SM_W2L = SM_W2H + 96 * STR;                  // 113152 (total 133120)
    extern __shared__ char sm[];
    int tid = threadIdx.x;
    int r0 = blockIdx.x * 128;

    stage_hi_lo(in, sm + SM_XH,  sm + SM_XL,  128, r0, nrows, tid, 256);
    stage_hi_lo(W1, sm + SM_W1H, sm + SM_W1L, 96, 0, 96, tid, 256);
    stage_hi_lo(W2, sm + SM_W2H, sm + SM_W2L, 96, 0, 96, tid, 256);
    __syncthreads();

    int w = tid >> 5, lane = tid & 31;
    int g = lane >> 2, tg = lane & 3;
    const int xoff = (w * 16 + g) * STR;

    float acc[NT][4];
    #pragma unroll
    for (int nt = 0; nt < NT; nt++) { acc[nt][0] = acc[nt][1] = acc[nt][2] = acc[nt][3] = 0.f; }

    // stage 1: H1 = relu(in @ W1^T + b1)
    mma_pass<NT>(sm + SM_XH + xoff, sm + SM_XL + xoff, sm + SM_W1H, sm + SM_W1L, g, tg, acc);
    __syncthreads();   // all warps done reading X; safe to overwrite

    // write H1 (relu'd) back as hi/lo bf16 into X tiles
    #pragma unroll
    for (int nt = 0; nt < NT; nt++) {
        int n0 = nt * 8 + 2 * tg;
        float2 bv = *reinterpret_cast<const float2*>(b1 + n0);
        float v0 = fmaxf(acc[nt][0] + bv.x, 0.f), v1 = fmaxf(acc[nt][1] + bv.y, 0.f);
        float v2 = fmaxf(acc[nt][2] + bv.x, 0.f), v3 = fmaxf(acc[nt][3] + bv.y, 0.f);
        int ra = (w * 16 + g) * STR + n0 * 2;
        int rb = (w * 16 + g + 8) * STR + n0 * 2;
        *reinterpret_cast<u32*>(sm + SM_XH + ra) = pack_hi(v0, v1);
        *reinterpret_cast<u32*>(sm + SM_XL + ra) = pack_lo(v0, v1);
        *reinterpret_cast<u32*>(sm + SM_XH + rb) = pack_hi(v2, v3);
        *reinterpret_cast<u32*>(sm + SM_XL + rb) = pack_lo(v2, v3);
    }
    __syncthreads();

    #pragma unroll
    for (int nt = 0; nt < NT; nt++) { acc[nt][0] = acc[nt][1] = acc[nt][2] = acc[nt][3] = 0.f; }

    // stage 2: out = H1 @ W2^T + b2 + res
    mma_pass<NT>(sm + SM_XH + xoff, sm + SM_XL + xoff, sm + SM_W2H, sm + SM_W2L, g, tg, acc);

    int row0 = r0 + w * 16 + g, row1 = row0 + 8;
    #pragma unroll
    for (int nt = 0; nt < NT; nt++) {
        int n0 = nt * 8 + 2 * tg;
        float2 bv = *reinterpret_cast<const float2*>(b2 + n0);
        if (row0 < nrows) {
            float2 rv = *reinterpret_cast<const float2*>(res + (size_t)row0 * HDIM + n0);
            *reinterpret_cast<float2*>(out + (size_t)row0 * HDIM + n0) =
                make_float2(acc[nt][0] + bv.x + rv.x, acc[nt][1] + bv.y + rv.y);
        }
        if (row1 < nrows) {
            float2 rv = *reinterpret_cast<const float2*>(res + (size_t)row1 * HDIM + n0);
            *reinterpret_cast<float2*>(out + (size_t)row1 * HDIM + n0) =
                make_float2(acc[nt][2] + bv.x + rv.x, acc[nt][3] + bv.y + rv.y);
        }
    }
}

// ---------------- GCN aggregation: one warp per dst node ----------------
__global__ void k_agg(const float* __restrict__ xw, const float* __restrict__ bias,
                      float* __restrict__ out)
{
    int warp = (blockIdx.x * blockDim.x + threadIdx.x) >> 5;
    int lane = threadIdx.x & 31;
    if (warp >= NNODES) return;
    int v = warp;
    int s = g_row_ptr[v], e = g_row_ptr[v + 1];
    float a0 = 0.f, a1 = 0.f, a2 = 0.f;
    int i = s;
    for (; i + 1 < e; i += 2) {
        int u0 = g_csr_src[i], u1 = g_csr_src[i + 1];
        float w0 = g_dis[u0], w1 = g_dis[u1];
        const float* r0p = xw + (size_t)u0 * HDIM;
        const float* r1p = xw + (size_t)u1 * HDIM;
        float x0 = r0p[lane], x1 = r0p[lane + 32], x2 = r0p[lane + 64];
        float y0 = r1p[lane], y1 = r1p[lane + 32], y2 = r1p[lane + 64];
        a0 += w0 * x0 + w1 * y0;
        a1 += w0 * x1 + w1 * y1;
        a2 += w0 * x2 + w1 * y2;
    }
    if (i < e) {
        int u = g_csr_src[i];
        float wn = g_dis[u];
        const float* r = xw + (size_t)u * HDIM;
        a0 += wn * r[lane];
        a1 += wn * r[lane + 32];
        a2 += wn * r[lane + 64];
    }
    float dv = g_dis[v];
    float iv = g_invdeg[v];
    const float* sr = xw + (size_t)v * HDIM;
    float* o = out + (size_t)v * HDIM;
    o[lane]      = a0 * dv + sr[lane]      * iv + bias[lane];
    o[lane + 32] = a1 * dv + sr[lane + 32] * iv + bias[lane + 32];
    o[lane + 64] = a2 * dv + sr[lane + 64] * iv + bias[lane + 64];
}

// ---------------- launch ----------------
extern "C" void kernel_launch(void* const* d_in, const int* in_sizes, int n_in,
                              void* d_out, int out_size)
{
    const float* x       = (const float*)d_in[0];
    const int*   t       = (const int*)  d_in[1];
    const int*   ei      = (const int*)  d_in[2];
    const float* emb     = (const float*)d_in[3];
    const float* fw_W    = (const float*)d_in[4];
    const float* fw_b    = (const float*)d_in[5];
    const float* pre_W   = (const float*)d_in[6];
    const float* pre_b   = (const float*)d_in[7];
    const float* conv_W  = (const float*)d_in[8];
    const float* conv_b  = (const float*)d_in[9];
    const float* post_W1 = (const float*)d_in[10];
    const float* post_b1 = (const float*)d_in[11];
    const float* post_W2 = (const float*)d_in[12];
    const float* post_b2 = (const float*)d_in[13];
    const float* fin_W   = (const float*)d_in[14];
    const float* fin_b   = (const float*)d_in[15];
    float* out = (float*)d_out;

    const int* src = ei;
    const int* dst = ei + NEDGES;

    float *A, *B, *C, *D, *Wc, *bc;
    cudaGetSymbolAddress((void**)&A,  g_bufA);
    cudaGetSymbolAddress((void**)&B,  g_bufB);
    cudaGetSymbolAddress((void**)&C,  g_bufC);
    cudaGetSymbolAddress((void**)&D,  g_bufD);
    cudaGetSymbolAddress((void**)&Wc, g_Wc);
    cudaGetSymbolAddress((void**)&bc, g_bc);

    const int SMEM96  = 2 * 128 * STR + 2 * 96 * STR;          // 93184
    const int SMEM32  = 2 * 128 * STR + 2 * 32 * STR;          // 66560
    const int SMEM2   = 2 * 128 * STR + 6 * 96 * STR;          // 133120
    cudaFuncSetAttribute(k_mma<96, F_BIAS>,          cudaFuncAttributeMaxDynamicSharedMemorySize, SMEM96);
    cudaFuncSetAttribute(k_mma<32, F_BIAS>,          cudaFuncAttributeMaxDynamicSharedMemorySize, SMEM32);
    cudaFuncSetAttribute(k_mma2,                     cudaFuncAttributeMaxDynamicSharedMemorySize, SMEM2);

    // fork: graph build on side stream, GEMM front-end on capture (null) stream
    cudaStream_t s2;
    cudaEvent_t eF, eJ;
    cudaStreamCreateWithFlags(&s2, cudaStreamNonBlocking);
    cudaEventCreateWithFlags(&eF, cudaEventDisableTiming);
    cudaEventCreateWithFlags(&eJ, cudaEventDisableTiming);

    cudaEventRecord(eF, 0);
    cudaStreamWaitEvent(s2, eF, 0);
    k_zero_deg  <<<(NNODES + 255) / 256, 256, 0, s2>>>();
    k_hist      <<<(NEDGES + 255) / 256, 256, 0, s2>>>(dst);
    k_scan_part <<<SCAN_NBLK, SCAN_B, 0, s2>>>();
    k_scan_mid  <<<1, 32, 0, s2>>>();
    k_scan_apply<<<SCAN_NBLK, SCAN_B, 0, s2>>>();
    k_scatter   <<<(NEDGES + 255) / 256, 256, 0, s2>>>(src, dst);
    cudaEventRecord(eJ, s2);

    const int GG = (NNODES + 127) / 128;
    const int AGG_BLOCKS = (NNODES * 32 + 255) / 256;

    // null stream: composes + first GEMM + layer-0 pre GEMM (independent of graph)
    k_compose<<<HDIM, HDIM>>>(pre_W,                pre_b,        conv_W,               emb, t, Wc,               bc);
    k_compose<<<HDIM, HDIM>>>(pre_W + HDIM * HDIM,  pre_b + HDIM, conv_W + HDIM * HDIM, emb, t, Wc + HDIM * HDIM, bc + HDIM);
    k_mma<96, F_BIAS><<<GG, 256, SMEM96>>>(x, fw_W, fw_b, nullptr, A, NNODES);
    k_mma<96, F_BIAS><<<GG, 256, SMEM96>>>(A, Wc, bc, nullptr, C, NNODES);

    cudaStreamWaitEvent(0, eJ, 0);   // join graph build before aggregation

    // layer 0
    k_agg<<<AGG_BLOCKS, 256>>>(C, conv_b, D);
    k_mma2<<<GG, 256, SMEM2>>>(D, post_W1, post_b1, post_W2, post_b2, A, B, NNODES);

    // layer 1
    k_mma<96, F_BIAS><<<GG, 256, SMEM96>>>(B, Wc + HDIM * HDIM, bc + HDIM, nullptr, C, NNODES);
    k_agg<<<AGG_BLOCKS, 256>>>(C, conv_b + HDIM, D);
    k_mma2<<<GG, 256, SMEM2>>>(D, post_W1 + HDIM * HDIM, post_b1 + HDIM,
                               post_W2 + HDIM * HDIM, post_b2 + HDIM, B, C, NNODES);

    // final
    k_mma<32, F_BIAS><<<GG, 256, SMEM32>>>(C, fin_W, fin_b, nullptr, out, NNODES);
}